// round 7
// baseline (speedup 1.0000x reference)
#include <cuda_runtime.h>
#include <math.h>

#define D 50
#define E 300
#define KNB 63
#define NMAX 20000
#define BROW 80        // padded weight row: 4 og * 20 floats (16 data + 4 pad)
#define ICH 10         // i-chunks
#define IPC 5          // i per chunk
#define PSTRIDE 52     // partial row stride (even -> float2 ok)
#define NT 128         // nodes per bilinear tile

// ---- device scratch ----
__device__ __align__(16) float g_ent[NMAX * D];
__device__ __align__(16) float g_part[ICH * NMAX * PSTRIDE];
__device__ __align__(16) float g_Wt2[D * D * BROW];
__device__ __align__(16) float g_WpT2[E * BROW];

// ---- f32x2 helpers ----
__device__ __forceinline__ void fma2(unsigned long long& acc,
                                     unsigned long long a,
                                     unsigned long long b) {
    asm("fma.rn.f32x2 %0, %1, %2, %0;" : "+l"(acc) : "l"(a), "l"(b));
}
__device__ __forceinline__ unsigned long long dup2(float x) {
    unsigned long long r;
    asm("mov.b64 %0, {%1, %1};" : "=l"(r) : "f"(x));
    return r;
}
__device__ __forceinline__ float2 unpack2(unsigned long long v) {
    float2 r;
    asm("mov.b64 {%0, %1}, %2;" : "=f"(r.x), "=f"(r.y) : "l"(v));
    return r;
}

// ============================================================
// Prep: pad/transpose weights into [row][80] og-grouped layout
// ============================================================
__global__ void prep_kernel(const float* __restrict__ Wp,
                            const float* __restrict__ Wbil) {
    int idx = blockIdx.x * blockDim.x + threadIdx.x;
    if (idx < D * D * BROW) {
        int r = idx / BROW, col = idx % BROW;
        int og = col / 20, cc = col % 20;
        int o = og * 16 + cc;
        int i = r / D, j = r % D;
        g_Wt2[idx] = (cc < 16 && o < D) ? Wbil[o * (D * D) + i * D + j] : 0.f;
    }
    if (idx < E * BROW) {
        int k = idx / BROW, col = idx % BROW;
        int og = col / 20, cc = col % 20;
        int o = og * 16 + cc;
        g_WpT2[idx] = (cc < 16 && o < D) ? Wp[o * E + k] : 0.f;
    }
}

// ============================================================
// Kernel A: ent = entity @ Wp^T + bp (f32x2 packed, R3-proven, unchanged)
// ============================================================
__global__ __launch_bounds__(128) void ent_proj_kernel(
    const float* __restrict__ entity, const float* __restrict__ bp, int N) {
    __shared__ __align__(16) float As[50 * 66];
    __shared__ __align__(16) float Bs[50 * BROW];
    int tid = threadIdx.x;
    int ng = tid >> 2, og = tid & 3;
    int n0 = blockIdx.x * 64;

    unsigned long long acc[2][8];
    #pragma unroll
    for (int s = 0; s < 2; s++)
        #pragma unroll
        for (int p = 0; p < 8; p++) acc[s][p] = 0ull;

    for (int c0 = 0; c0 < E; c0 += 50) {
        __syncthreads();
        for (int idx = tid; idx < 64 * 50; idx += 128) {
            int n = idx / 50, k = idx % 50;
            int gn = n0 + n;
            As[k * 66 + n] = (gn < N) ? entity[(size_t)gn * E + c0 + k] : 0.f;
        }
        for (int idx = tid; idx < 50 * BROW; idx += 128)
            Bs[idx] = g_WpT2[(size_t)c0 * BROW + idx];
        __syncthreads();
        #pragma unroll 10
        for (int k = 0; k < 50; k++) {
            float2 ap = *(const float2*)&As[k * 66 + 2 * ng];
            unsigned long long aA = dup2(ap.x), aB = dup2(ap.y);
            const ulonglong2* bpp = (const ulonglong2*)&Bs[k * BROW + og * 20];
            ulonglong2 u0 = bpp[0], u1 = bpp[1], u2 = bpp[2], u3 = bpp[3];
            fma2(acc[0][0], aA, u0.x); fma2(acc[0][1], aA, u0.y);
            fma2(acc[0][2], aA, u1.x); fma2(acc[0][3], aA, u1.y);
            fma2(acc[0][4], aA, u2.x); fma2(acc[0][5], aA, u2.y);
            fma2(acc[0][6], aA, u3.x); fma2(acc[0][7], aA, u3.y);
            fma2(acc[1][0], aB, u0.x); fma2(acc[1][1], aB, u0.y);
            fma2(acc[1][2], aB, u1.x); fma2(acc[1][3], aB, u1.y);
            fma2(acc[1][4], aB, u2.x); fma2(acc[1][5], aB, u2.y);
            fma2(acc[1][6], aB, u3.x); fma2(acc[1][7], aB, u3.y);
        }
    }
    #pragma unroll
    for (int s = 0; s < 2; s++) {
        int n = n0 + 2 * ng + s;
        if (n >= N) continue;
        #pragma unroll
        for (int p = 0; p < 8; p++) {
            int o = og * 16 + 2 * p;
            float2 v = unpack2(acc[s][p]);
            if (o < D)     g_ent[(size_t)n * D + o]     = v.x + bp[o];
            if (o + 1 < D) g_ent[(size_t)n * D + o + 1] = v.y + bp[o + 1];
        }
    }
}

// ============================================================
// Kernel B v3: bilinear with persistent weight slab.
// grid = (node tiles of 128, ICH chunks of IPC i's).
// Block: 256 threads, thread = 2 nodes x 16 outputs.
// Slab (IPC*50*BROW floats = 80KB) loaded ONCE, no refills in main loop.
// Dynamic smem layout: [slab 80000B][es 26000B][qs 2600B+pad]
// ============================================================
__global__ __launch_bounds__(256) void bilinear_kernel(
    const float* __restrict__ query, int N) {
    extern __shared__ __align__(16) float sm[];
    float* slab = sm;                         // IPC*50*BROW = 20000 floats
    float* es   = sm + IPC * 50 * BROW;       // 50 rows x 130
    float* qs   = es + 50 * 130;              // IPC rows x 130
    int tid = threadIdx.x;
    int ng = tid >> 2, og = tid & 3;          // node pair 0..63, out-group 0..3
    int n0 = blockIdx.x * NT;
    int i0 = blockIdx.y * IPC;
    float* outbuf = g_part + (size_t)blockIdx.y * (NMAX * PSTRIDE);

    // one-time slab load (contiguous region of g_Wt2)
    {
        const float4* src = (const float4*)(g_Wt2 + (size_t)(i0 * 50) * BROW);
        float4* dst = (float4*)slab;
        for (int c = tid; c < IPC * 50 * BROW / 4; c += 256)
            dst[c] = src[c];
    }
    // node tiles: es transposed [x][node], qs [ii][node]
    for (int idx = tid; idx < NT * 50; idx += 256) {
        int n = idx / 50, x = idx % 50;
        int gn = n0 + n;
        es[x * 130 + n] = (gn < N) ? g_ent[(size_t)gn * D + x] : 0.f;
    }
    for (int idx = tid; idx < NT * IPC; idx += 256) {
        int n = idx / IPC, x = idx % IPC;
        int gn = n0 + n;
        qs[x * 130 + n] = (gn < N) ? query[(size_t)gn * D + i0 + x] : 0.f;
    }
    __syncthreads();

    unsigned long long acc[2][8];
    #pragma unroll
    for (int s = 0; s < 2; s++)
        #pragma unroll
        for (int p = 0; p < 8; p++) acc[s][p] = 0ull;

    #pragma unroll
    for (int ii = 0; ii < IPC; ii++) {
        float2 qp = *(const float2*)&qs[ii * 130 + 2 * ng];
        const float* Bbase = slab + (size_t)(ii * 50) * BROW + og * 20;
        #pragma unroll 10
        for (int j = 0; j < 50; j++) {
            float2 ep = *(const float2*)&es[j * 130 + 2 * ng];
            unsigned long long aA = dup2(qp.x * ep.x);
            unsigned long long aB = dup2(qp.y * ep.y);
            const ulonglong2* bpp = (const ulonglong2*)(Bbase + j * BROW);
            ulonglong2 u0 = bpp[0], u1 = bpp[1], u2 = bpp[2], u3 = bpp[3];
            fma2(acc[0][0], aA, u0.x); fma2(acc[0][1], aA, u0.y);
            fma2(acc[0][2], aA, u1.x); fma2(acc[0][3], aA, u1.y);
            fma2(acc[0][4], aA, u2.x); fma2(acc[0][5], aA, u2.y);
            fma2(acc[0][6], aA, u3.x); fma2(acc[0][7], aA, u3.y);
            fma2(acc[1][0], aB, u0.x); fma2(acc[1][1], aB, u0.y);
            fma2(acc[1][2], aB, u1.x); fma2(acc[1][3], aB, u1.y);
            fma2(acc[1][4], aB, u2.x); fma2(acc[1][5], aB, u2.y);
            fma2(acc[1][6], aB, u3.x); fma2(acc[1][7], aB, u3.y);
        }
    }

    #pragma unroll
    for (int s = 0; s < 2; s++) {
        int n = n0 + 2 * ng + s;
        if (n >= N) continue;
        #pragma unroll
        for (int p = 0; p < 8; p++) {
            int o = og * 16 + 2 * p;
            float2 v = unpack2(acc[s][p]);
            if (o < D)     outbuf[(size_t)n * PSTRIDE + o]     = v.x;
            if (o + 1 < D) outbuf[(size_t)n * PSTRIDE + o + 1] = v.y;
        }
    }
}

// ============================================================
// Kernel C: fused tail. 16 nodes/block, 512 threads, warp per node
// (per-warp code identical to proven R6 version; sums ICH partials + bbil).
// ============================================================
__global__ __launch_bounds__(512) void tail_kernel(
    const float* __restrict__ nbr, const float* __restrict__ scores,
    const float* __restrict__ bbil,
    const float* __restrict__ Wg, const float* __restrict__ g_bias,
    const float* __restrict__ Wr, const float* __restrict__ br,
    float* __restrict__ out, int N) {
    __shared__ __align__(16) float Wgs[50 * 51];
    __shared__ __align__(16) float s_sm[16][50];
    __shared__ __align__(16) float Wrs[50];
    __shared__ __align__(16) float gbs[50];
    __shared__ __align__(16) float bbs[52];
    int tid = threadIdx.x;

    for (int idx = tid; idx < 2500; idx += 512) {
        int o = idx / 50, d = idx % 50;
        Wgs[o * 51 + d] = Wg[idx];
    }
    if (tid < 50) { Wrs[tid] = Wr[tid]; gbs[tid] = g_bias[tid]; bbs[tid] = bbil[tid]; }
    __syncthreads();

    int warp = tid >> 5, lane = tid & 31;
    int n = blockIdx.x * 16 + warp;
    if (n >= N) return;

    const float* base = nbr + (size_t)n * KNB * D;
    const float* sc   = scores + (size_t)n * (KNB + 1);

    if (lane < 25) {
        float wK = sc[KNB];
        float nx = bbs[2 * lane], ny = bbs[2 * lane + 1];
        #pragma unroll
        for (int c = 0; c < ICH; c++) {
            float2 v = *(const float2*)&g_part[(size_t)c * (NMAX * PSTRIDE)
                                               + (size_t)n * PSTRIDE + 2 * lane];
            nx += v.x; ny += v.y;
        }
        float sx = wK * nx, sy = wK * ny;
        float tx_ = 0.f, ty_ = 0.f;
        #pragma unroll
        for (int k = 0; k < 62; k += 2) {
            float w0 = sc[k], w1 = sc[k + 1];
            float2 u0 = *(const float2*)(base + (size_t)k * D + 2 * lane);
            float2 u1 = *(const float2*)(base + (size_t)(k + 1) * D + 2 * lane);
            sx += w0 * u0.x; sy += w0 * u0.y;
            tx_ += w1 * u1.x; ty_ += w1 * u1.y;
        }
        {
            float w = sc[62];
            float2 u = *(const float2*)(base + (size_t)62 * D + 2 * lane);
            sx += w * u.x; sy += w * u.y;
        }
        s_sm[warp][2 * lane]     = sx + tx_;
        s_sm[warp][2 * lane + 1] = sy + ty_;
    }
    __syncwarp();

    float r = 0.f;
    #pragma unroll
    for (int rep = 0; rep < 2; rep++) {
        int o = lane + 32 * rep;
        if (o < D) {
            float a = gbs[o];
            #pragma unroll 10
            for (int d = 0; d < D; d++)
                a += s_sm[warp][d] * Wgs[o * 51 + d];
            float f = (a > 0.f) ? a : expm1f(a);
            r += f * Wrs[o];
        }
    }
    #pragma unroll
    for (int off = 16; off; off >>= 1)
        r += __shfl_down_sync(0xffffffffu, r, off);
    if (lane == 0) out[n] = r + br[0];
}

// ============================================================
extern "C" void kernel_launch(void* const* d_in, const int* in_sizes, int n_in,
                              void* d_out, int out_size) {
    const float* query  = (const float*)d_in[0];
    const float* entity = (const float*)d_in[1];
    const float* nbr    = (const float*)d_in[2];
    const float* scores = (const float*)d_in[3];
    const float* Wp     = (const float*)d_in[4];
    const float* bp     = (const float*)d_in[5];
    const float* Wbil   = (const float*)d_in[6];
    const float* bbil   = (const float*)d_in[7];
    const float* Wg     = (const float*)d_in[8];
    const float* gbias  = (const float*)d_in[9];
    const float* Wr     = (const float*)d_in[10];
    const float* br     = (const float*)d_in[11];
    float* out = (float*)d_out;

    int N = in_sizes[0] / D;
    if (N > NMAX) N = NMAX;

    // dyn smem: slab 80000 + es 26000 + qs 2600 -> 108600 B
    const int BIL_SMEM = (IPC * 50 * BROW + 50 * 130 + IPC * 130) * 4;
    cudaFuncSetAttribute(bilinear_kernel,
                         cudaFuncAttributeMaxDynamicSharedMemorySize, BIL_SMEM);

    prep_kernel<<<(D * D * BROW + 255) / 256, 256>>>(Wp, Wbil);
    ent_proj_kernel<<<(N + 63) / 64, 128>>>(entity, bp, N);
    dim3 bgrid((N + NT - 1) / NT, ICH);
    bilinear_kernel<<<bgrid, 256, BIL_SMEM>>>(query, N);
    tail_kernel<<<(N + 15) / 16, 512>>>(nbr, scores, bbil, Wg, gbias, Wr, br, out, N);
}

// round 8
// speedup vs baseline: 1.4981x; 1.4981x over previous
#include <cuda_runtime.h>
#include <math.h>

#define D 50
#define E 300
#define KNB 63
#define NMAX 20000
#define BROW 80    // padded weight row: 4 og * 20 floats (16 data + 4 pad)
#define ISPL 5     // i-range splits (blocks along y)
#define IPB 10     // i's per block

// ---- device scratch ----
__device__ __align__(16) float g_ent[NMAX * D];
__device__ __align__(16) float g_part[ISPL * NMAX * D];   // bilinear partials
__device__ __align__(16) float g_Wt2[D * D * BROW];
__device__ __align__(16) float g_WpT2[E * BROW];

// ---- f32x2 helpers ----
__device__ __forceinline__ void fma2(unsigned long long& acc,
                                     unsigned long long a,
                                     unsigned long long b) {
    asm("fma.rn.f32x2 %0, %1, %2, %0;" : "+l"(acc) : "l"(a), "l"(b));
}
__device__ __forceinline__ unsigned long long dup2(float x) {
    unsigned long long r;
    asm("mov.b64 %0, {%1, %1};" : "=l"(r) : "f"(x));
    return r;
}
__device__ __forceinline__ float2 unpack2(unsigned long long v) {
    float2 r;
    asm("mov.b64 {%0, %1}, %2;" : "=f"(r.x), "=f"(r.y) : "l"(v));
    return r;
}

// ============================================================
// Prep: pad/transpose weights into [row][80] og-grouped layout
// ============================================================
__global__ void prep_kernel(const float* __restrict__ Wp,
                            const float* __restrict__ Wbil) {
    int idx = blockIdx.x * blockDim.x + threadIdx.x;
    if (idx < D * D * BROW) {
        int r = idx / BROW, col = idx % BROW;
        int og = col / 20, cc = col % 20;
        int o = og * 16 + cc;
        int i = r / D, j = r % D;
        g_Wt2[idx] = (cc < 16 && o < D) ? Wbil[o * (D * D) + i * D + j] : 0.f;
    }
    if (idx < E * BROW) {
        int k = idx / BROW, col = idx % BROW;
        int og = col / 20, cc = col % 20;
        int o = og * 16 + cc;
        g_WpT2[idx] = (cc < 16 && o < D) ? Wp[o * E + k] : 0.f;
    }
}

// ============================================================
// Kernel A: ent = entity @ Wp^T + bp (f32x2 packed, R3-proven, unchanged)
// ============================================================
__global__ __launch_bounds__(128) void ent_proj_kernel(
    const float* __restrict__ entity, const float* __restrict__ bp, int N) {
    __shared__ __align__(16) float As[50 * 66];
    __shared__ __align__(16) float Bs[50 * BROW];
    int tid = threadIdx.x;
    int ng = tid >> 2, og = tid & 3;
    int n0 = blockIdx.x * 64;

    unsigned long long acc[2][8];
    #pragma unroll
    for (int s = 0; s < 2; s++)
        #pragma unroll
        for (int p = 0; p < 8; p++) acc[s][p] = 0ull;

    for (int c0 = 0; c0 < E; c0 += 50) {
        __syncthreads();
        for (int idx = tid; idx < 64 * 50; idx += 128) {
            int n = idx / 50, k = idx % 50;
            int gn = n0 + n;
            As[k * 66 + n] = (gn < N) ? entity[(size_t)gn * E + c0 + k] : 0.f;
        }
        for (int idx = tid; idx < 50 * BROW; idx += 128)
            Bs[idx] = g_WpT2[(size_t)c0 * BROW + idx];
        __syncthreads();
        #pragma unroll 10
        for (int k = 0; k < 50; k++) {
            float2 ap = *(const float2*)&As[k * 66 + 2 * ng];
            unsigned long long aA = dup2(ap.x), aB = dup2(ap.y);
            const ulonglong2* bpp = (const ulonglong2*)&Bs[k * BROW + og * 20];
            ulonglong2 u0 = bpp[0], u1 = bpp[1], u2 = bpp[2], u3 = bpp[3];
            fma2(acc[0][0], aA, u0.x); fma2(acc[0][1], aA, u0.y);
            fma2(acc[0][2], aA, u1.x); fma2(acc[0][3], aA, u1.y);
            fma2(acc[0][4], aA, u2.x); fma2(acc[0][5], aA, u2.y);
            fma2(acc[0][6], aA, u3.x); fma2(acc[0][7], aA, u3.y);
            fma2(acc[1][0], aB, u0.x); fma2(acc[1][1], aB, u0.y);
            fma2(acc[1][2], aB, u1.x); fma2(acc[1][3], aB, u1.y);
            fma2(acc[1][4], aB, u2.x); fma2(acc[1][5], aB, u2.y);
            fma2(acc[1][6], aB, u3.x); fma2(acc[1][7], aB, u3.y);
        }
    }
    #pragma unroll
    for (int s = 0; s < 2; s++) {
        int n = n0 + 2 * ng + s;
        if (n >= N) continue;
        #pragma unroll
        for (int p = 0; p < 8; p++) {
            int o = og * 16 + 2 * p;
            float2 v = unpack2(acc[s][p]);
            if (o < D)     g_ent[(size_t)n * D + o]     = v.x + bp[o];
            if (o + 1 < D) g_ent[(size_t)n * D + o + 1] = v.y + bp[o + 1];
        }
    }
}

// ============================================================
// Kernel B: bilinear, R6 inner loop byte-identical; i-range split ISPL ways
// (blockIdx.y -> i in [y*IPB, y*IPB+IPB), partial to g_part[y]).
// block: 64 nodes, 128 threads; thread: 2 nodes x 16 outputs.
// ============================================================
__global__ __launch_bounds__(128) void bilinear_kernel(
    const float* __restrict__ query, int N) {
    __shared__ __align__(16) float qs[IPB * 66 + 2];
    __shared__ __align__(16) float es[50 * 66];
    __shared__ __align__(16) float Bs[50 * BROW];
    int tid = threadIdx.x;
    int ng = tid >> 2, og = tid & 3;
    int n0 = blockIdx.x * 64;
    int i0 = blockIdx.y * IPB;
    float* outbuf = g_part + (size_t)blockIdx.y * (NMAX * D);

    for (int idx = tid; idx < 64 * 50; idx += 128) {
        int n = idx / 50, x = idx % 50;
        int gn = n0 + n;
        es[x * 66 + n] = (gn < N) ? g_ent[(size_t)gn * D + x] : 0.f;
    }
    for (int idx = tid; idx < 64 * IPB; idx += 128) {
        int n = idx / IPB, x = idx % IPB;
        int gn = n0 + n;
        qs[x * 66 + n] = (gn < N) ? query[(size_t)gn * D + i0 + x] : 0.f;
    }

    unsigned long long acc[2][8];
    #pragma unroll
    for (int s = 0; s < 2; s++)
        #pragma unroll
        for (int p = 0; p < 8; p++) acc[s][p] = 0ull;

    for (int ii = 0; ii < IPB; ii++) {
        __syncthreads();
        const float* src = g_Wt2 + (size_t)((i0 + ii) * D) * BROW;
        for (int idx = tid; idx < 50 * BROW; idx += 128)
            Bs[idx] = src[idx];
        __syncthreads();
        float2 qp = *(const float2*)&qs[ii * 66 + 2 * ng];
        #pragma unroll 10
        for (int j = 0; j < 50; j++) {
            float2 ep = *(const float2*)&es[j * 66 + 2 * ng];
            unsigned long long aA = dup2(qp.x * ep.x);
            unsigned long long aB = dup2(qp.y * ep.y);
            const ulonglong2* bpp = (const ulonglong2*)&Bs[j * BROW + og * 20];
            ulonglong2 u0 = bpp[0], u1 = bpp[1], u2 = bpp[2], u3 = bpp[3];
            fma2(acc[0][0], aA, u0.x); fma2(acc[0][1], aA, u0.y);
            fma2(acc[0][2], aA, u1.x); fma2(acc[0][3], aA, u1.y);
            fma2(acc[0][4], aA, u2.x); fma2(acc[0][5], aA, u2.y);
            fma2(acc[0][6], aA, u3.x); fma2(acc[0][7], aA, u3.y);
            fma2(acc[1][0], aB, u0.x); fma2(acc[1][1], aB, u0.y);
            fma2(acc[1][2], aB, u1.x); fma2(acc[1][3], aB, u1.y);
            fma2(acc[1][4], aB, u2.x); fma2(acc[1][5], aB, u2.y);
            fma2(acc[1][6], aB, u3.x); fma2(acc[1][7], aB, u3.y);
        }
    }

    #pragma unroll
    for (int s = 0; s < 2; s++) {
        int n = n0 + 2 * ng + s;
        if (n >= N) continue;
        #pragma unroll
        for (int p = 0; p < 8; p++) {
            int o = og * 16 + 2 * p;
            float2 v = unpack2(acc[s][p]);
            if (o < D)     outbuf[(size_t)n * D + o]     = v.x;
            if (o + 1 < D) outbuf[(size_t)n * D + o + 1] = v.y;
        }
    }
}

// ============================================================
// Kernel C: fused tail (R6-proven structure; sums ISPL partials + bbil)
// block: 8 nodes, 256 threads, 1 warp/node, lanes 0..24 active in phase 1
// ============================================================
__global__ __launch_bounds__(256) void tail_kernel(
    const float* __restrict__ nbr, const float* __restrict__ scores,
    const float* __restrict__ bbil,
    const float* __restrict__ Wg, const float* __restrict__ g_bias,
    const float* __restrict__ Wr, const float* __restrict__ br,
    float* __restrict__ out, int N) {
    __shared__ __align__(16) float Wgs[50 * 51];
    __shared__ __align__(16) float s_sm[8][50];
    __shared__ __align__(16) float Wrs[50];
    __shared__ __align__(16) float gbs[50];
    __shared__ __align__(16) float bbs[52];
    int tid = threadIdx.x;

    for (int idx = tid; idx < 2500; idx += 256) {
        int o = idx / 50, d = idx % 50;
        Wgs[o * 51 + d] = Wg[idx];
    }
    if (tid < 50) { Wrs[tid] = Wr[tid]; gbs[tid] = g_bias[tid]; bbs[tid] = bbil[tid]; }
    __syncthreads();

    int warp = tid >> 5, lane = tid & 31;
    int n = blockIdx.x * 8 + warp;
    if (n >= N) return;

    const float* base = nbr + (size_t)n * KNB * D;
    const float* sc   = scores + (size_t)n * (KNB + 1);

    if (lane < 25) {
        float wK = sc[KNB];
        float nx = bbs[2 * lane], ny = bbs[2 * lane + 1];
        #pragma unroll
        for (int c = 0; c < ISPL; c++) {
            float2 v = *(const float2*)&g_part[(size_t)c * (NMAX * D)
                                               + (size_t)n * D + 2 * lane];
            nx += v.x; ny += v.y;
        }
        float sx = wK * nx, sy = wK * ny;
        float tx_ = 0.f, ty_ = 0.f;
        #pragma unroll
        for (int k = 0; k < 62; k += 2) {
            float w0 = sc[k], w1 = sc[k + 1];
            float2 u0 = *(const float2*)(base + (size_t)k * D + 2 * lane);
            float2 u1 = *(const float2*)(base + (size_t)(k + 1) * D + 2 * lane);
            sx += w0 * u0.x; sy += w0 * u0.y;
            tx_ += w1 * u1.x; ty_ += w1 * u1.y;
        }
        {
            float w = sc[62];
            float2 u = *(const float2*)(base + (size_t)62 * D + 2 * lane);
            sx += w * u.x; sy += w * u.y;
        }
        s_sm[warp][2 * lane]     = sx + tx_;
        s_sm[warp][2 * lane + 1] = sy + ty_;
    }
    __syncwarp();

    float r = 0.f;
    #pragma unroll
    for (int rep = 0; rep < 2; rep++) {
        int o = lane + 32 * rep;
        if (o < D) {
            float a = gbs[o];
            #pragma unroll 10
            for (int d = 0; d < D; d++)
                a += s_sm[warp][d] * Wgs[o * 51 + d];
            float f = (a > 0.f) ? a : expm1f(a);
            r += f * Wrs[o];
        }
    }
    #pragma unroll
    for (int off = 16; off; off >>= 1)
        r += __shfl_down_sync(0xffffffffu, r, off);
    if (lane == 0) out[n] = r + br[0];
}

// ============================================================
extern "C" void kernel_launch(void* const* d_in, const int* in_sizes, int n_in,
                              void* d_out, int out_size) {
    const float* query  = (const float*)d_in[0];
    const float* entity = (const float*)d_in[1];
    const float* nbr    = (const float*)d_in[2];
    const float* scores = (const float*)d_in[3];
    const float* Wp     = (const float*)d_in[4];
    const float* bp     = (const float*)d_in[5];
    const float* Wbil   = (const float*)d_in[6];
    const float* bbil   = (const float*)d_in[7];
    const float* Wg     = (const float*)d_in[8];
    const float* gbias  = (const float*)d_in[9];
    const float* Wr     = (const float*)d_in[10];
    const float* br     = (const float*)d_in[11];
    float* out = (float*)d_out;

    int N = in_sizes[0] / D;
    if (N > NMAX) N = NMAX;

    prep_kernel<<<(D * D * BROW + 255) / 256, 256>>>(Wp, Wbil);
    ent_proj_kernel<<<(N + 63) / 64, 128>>>(entity, bp, N);
    dim3 bgrid((N + 63) / 64, ISPL);
    bilinear_kernel<<<bgrid, 128>>>(query, N);
    tail_kernel<<<(N + 7) / 8, 256>>>(nbr, scores, bbil, Wg, gbias, Wr, br, out, N);
}

// round 9
// speedup vs baseline: 1.5416x; 1.0291x over previous
#include <cuda_runtime.h>
#include <math.h>

#define D 50
#define E 300
#define KNB 63
#define NMAX 20000
#define BROW 80    // padded weight row: 4 og * 20 floats (16 data + 4 pad)
#define ISPL 10    // i-range splits (blocks along y)
#define IPB 5      // i's per block

// ---- device scratch ----
__device__ __align__(16) float g_ent[NMAX * D];
__device__ __align__(16) float g_part[ISPL * NMAX * D];   // bilinear partials
__device__ __align__(16) float g_Wt2[D * D * BROW];
__device__ __align__(16) float g_WpT2[E * BROW];

// ---- f32x2 helpers ----
__device__ __forceinline__ void fma2(unsigned long long& acc,
                                     unsigned long long a,
                                     unsigned long long b) {
    asm("fma.rn.f32x2 %0, %1, %2, %0;" : "+l"(acc) : "l"(a), "l"(b));
}
__device__ __forceinline__ unsigned long long dup2(float x) {
    unsigned long long r;
    asm("mov.b64 %0, {%1, %1};" : "=l"(r) : "f"(x));
    return r;
}
__device__ __forceinline__ float2 unpack2(unsigned long long v) {
    float2 r;
    asm("mov.b64 {%0, %1}, %2;" : "=f"(r.x), "=f"(r.y) : "l"(v));
    return r;
}

// ============================================================
// Prep: pad/transpose weights into [row][80] og-grouped layout
// ============================================================
__global__ void prep_kernel(const float* __restrict__ Wp,
                            const float* __restrict__ Wbil) {
    int idx = blockIdx.x * blockDim.x + threadIdx.x;
    if (idx < D * D * BROW) {
        int r = idx / BROW, col = idx % BROW;
        int og = col / 20, cc = col % 20;
        int o = og * 16 + cc;
        int i = r / D, j = r % D;
        g_Wt2[idx] = (cc < 16 && o < D) ? Wbil[o * (D * D) + i * D + j] : 0.f;
    }
    if (idx < E * BROW) {
        int k = idx / BROW, col = idx % BROW;
        int og = col / 20, cc = col % 20;
        int o = og * 16 + cc;
        g_WpT2[idx] = (cc < 16 && o < D) ? Wp[o * E + k] : 0.f;
    }
}

// ============================================================
// Kernel A: ent = entity @ Wp^T + bp (f32x2 packed, R3-proven, unchanged)
// ============================================================
__global__ __launch_bounds__(128) void ent_proj_kernel(
    const float* __restrict__ entity, const float* __restrict__ bp, int N) {
    __shared__ __align__(16) float As[50 * 66];
    __shared__ __align__(16) float Bs[50 * BROW];
    int tid = threadIdx.x;
    int ng = tid >> 2, og = tid & 3;
    int n0 = blockIdx.x * 64;

    unsigned long long acc[2][8];
    #pragma unroll
    for (int s = 0; s < 2; s++)
        #pragma unroll
        for (int p = 0; p < 8; p++) acc[s][p] = 0ull;

    for (int c0 = 0; c0 < E; c0 += 50) {
        __syncthreads();
        for (int idx = tid; idx < 64 * 50; idx += 128) {
            int n = idx / 50, k = idx % 50;
            int gn = n0 + n;
            As[k * 66 + n] = (gn < N) ? entity[(size_t)gn * E + c0 + k] : 0.f;
        }
        for (int idx = tid; idx < 50 * BROW / 4; idx += 128)
            ((float4*)Bs)[idx] = ((const float4*)(g_WpT2 + (size_t)c0 * BROW))[idx];
        __syncthreads();
        #pragma unroll 10
        for (int k = 0; k < 50; k++) {
            float2 ap = *(const float2*)&As[k * 66 + 2 * ng];
            unsigned long long aA = dup2(ap.x), aB = dup2(ap.y);
            const ulonglong2* bpp = (const ulonglong2*)&Bs[k * BROW + og * 20];
            ulonglong2 u0 = bpp[0], u1 = bpp[1], u2 = bpp[2], u3 = bpp[3];
            fma2(acc[0][0], aA, u0.x); fma2(acc[0][1], aA, u0.y);
            fma2(acc[0][2], aA, u1.x); fma2(acc[0][3], aA, u1.y);
            fma2(acc[0][4], aA, u2.x); fma2(acc[0][5], aA, u2.y);
            fma2(acc[0][6], aA, u3.x); fma2(acc[0][7], aA, u3.y);
            fma2(acc[1][0], aB, u0.x); fma2(acc[1][1], aB, u0.y);
            fma2(acc[1][2], aB, u1.x); fma2(acc[1][3], aB, u1.y);
            fma2(acc[1][4], aB, u2.x); fma2(acc[1][5], aB, u2.y);
            fma2(acc[1][6], aB, u3.x); fma2(acc[1][7], aB, u3.y);
        }
    }
    #pragma unroll
    for (int s = 0; s < 2; s++) {
        int n = n0 + 2 * ng + s;
        if (n >= N) continue;
        #pragma unroll
        for (int p = 0; p < 8; p++) {
            int o = og * 16 + 2 * p;
            float2 v = unpack2(acc[s][p]);
            if (o < D)     g_ent[(size_t)n * D + o]     = v.x + bp[o];
            if (o + 1 < D) g_ent[(size_t)n * D + o + 1] = v.y + bp[o + 1];
        }
    }
}

// ============================================================
// Kernel B: bilinear, proven inner loop; i-split ISPL=10, float4 refill.
// block: 64 nodes, 128 threads; thread: 2 nodes x 16 outputs.
// ============================================================
__global__ __launch_bounds__(128) void bilinear_kernel(
    const float* __restrict__ query, int N) {
    __shared__ __align__(16) float qs[IPB * 66 + 2];
    __shared__ __align__(16) float es[50 * 66];
    __shared__ __align__(16) float Bs[50 * BROW];
    int tid = threadIdx.x;
    int ng = tid >> 2, og = tid & 3;
    int n0 = blockIdx.x * 64;
    int i0 = blockIdx.y * IPB;
    float* outbuf = g_part + (size_t)blockIdx.y * (NMAX * D);

    for (int idx = tid; idx < 64 * 50; idx += 128) {
        int n = idx / 50, x = idx % 50;
        int gn = n0 + n;
        es[x * 66 + n] = (gn < N) ? g_ent[(size_t)gn * D + x] : 0.f;
    }
    for (int idx = tid; idx < 64 * IPB; idx += 128) {
        int n = idx / IPB, x = idx % IPB;
        int gn = n0 + n;
        qs[x * 66 + n] = (gn < N) ? query[(size_t)gn * D + i0 + x] : 0.f;
    }

    unsigned long long acc[2][8];
    #pragma unroll
    for (int s = 0; s < 2; s++)
        #pragma unroll
        for (int p = 0; p < 8; p++) acc[s][p] = 0ull;

    for (int ii = 0; ii < IPB; ii++) {
        __syncthreads();
        {   // vectorized refill: 1000 float4s, ~8 per thread
            const float4* src = (const float4*)(g_Wt2 + (size_t)((i0 + ii) * D) * BROW);
            float4* dst = (float4*)Bs;
            #pragma unroll
            for (int c = tid; c < 50 * BROW / 4; c += 128)
                dst[c] = src[c];
        }
        __syncthreads();
        float2 qp = *(const float2*)&qs[ii * 66 + 2 * ng];
        #pragma unroll 10
        for (int j = 0; j < 50; j++) {
            float2 ep = *(const float2*)&es[j * 66 + 2 * ng];
            unsigned long long aA = dup2(qp.x * ep.x);
            unsigned long long aB = dup2(qp.y * ep.y);
            const ulonglong2* bpp = (const ulonglong2*)&Bs[j * BROW + og * 20];
            ulonglong2 u0 = bpp[0], u1 = bpp[1], u2 = bpp[2], u3 = bpp[3];
            fma2(acc[0][0], aA, u0.x); fma2(acc[0][1], aA, u0.y);
            fma2(acc[0][2], aA, u1.x); fma2(acc[0][3], aA, u1.y);
            fma2(acc[0][4], aA, u2.x); fma2(acc[0][5], aA, u2.y);
            fma2(acc[0][6], aA, u3.x); fma2(acc[0][7], aA, u3.y);
            fma2(acc[1][0], aB, u0.x); fma2(acc[1][1], aB, u0.y);
            fma2(acc[1][2], aB, u1.x); fma2(acc[1][3], aB, u1.y);
            fma2(acc[1][4], aB, u2.x); fma2(acc[1][5], aB, u2.y);
            fma2(acc[1][6], aB, u3.x); fma2(acc[1][7], aB, u3.y);
        }
    }

    #pragma unroll
    for (int s = 0; s < 2; s++) {
        int n = n0 + 2 * ng + s;
        if (n >= N) continue;
        #pragma unroll
        for (int p = 0; p < 8; p++) {
            int o = og * 16 + 2 * p;
            float2 v = unpack2(acc[s][p]);
            if (o < D)     outbuf[(size_t)n * D + o]     = v.x;
            if (o + 1 < D) outbuf[(size_t)n * D + o + 1] = v.y;
        }
    }
}

// ============================================================
// Kernel C: fused tail (R6-proven structure; sums ISPL partials + bbil)
// block: 8 nodes, 256 threads, 1 warp/node, lanes 0..24 active in phase 1
// ============================================================
__global__ __launch_bounds__(256) void tail_kernel(
    const float* __restrict__ nbr, const float* __restrict__ scores,
    const float* __restrict__ bbil,
    const float* __restrict__ Wg, const float* __restrict__ g_bias,
    const float* __restrict__ Wr, const float* __restrict__ br,
    float* __restrict__ out, int N) {
    __shared__ __align__(16) float Wgs[50 * 51];
    __shared__ __align__(16) float s_sm[8][50];
    __shared__ __align__(16) float Wrs[50];
    __shared__ __align__(16) float gbs[50];
    __shared__ __align__(16) float bbs[52];
    int tid = threadIdx.x;

    for (int idx = tid; idx < 2500; idx += 256) {
        int o = idx / 50, d = idx % 50;
        Wgs[o * 51 + d] = Wg[idx];
    }
    if (tid < 50) { Wrs[tid] = Wr[tid]; gbs[tid] = g_bias[tid]; bbs[tid] = bbil[tid]; }
    __syncthreads();

    int warp = tid >> 5, lane = tid & 31;
    int n = blockIdx.x * 8 + warp;
    if (n >= N) return;

    const float* base = nbr + (size_t)n * KNB * D;
    const float* sc   = scores + (size_t)n * (KNB + 1);

    if (lane < 25) {
        float wK = sc[KNB];
        float nx = bbs[2 * lane], ny = bbs[2 * lane + 1];
        #pragma unroll
        for (int c = 0; c < ISPL; c++) {
            float2 v = *(const float2*)&g_part[(size_t)c * (NMAX * D)
                                               + (size_t)n * D + 2 * lane];
            nx += v.x; ny += v.y;
        }
        float sx = wK * nx, sy = wK * ny;
        float tx_ = 0.f, ty_ = 0.f;
        #pragma unroll
        for (int k = 0; k < 62; k += 2) {
            float w0 = sc[k], w1 = sc[k + 1];
            float2 u0 = *(const float2*)(base + (size_t)k * D + 2 * lane);
            float2 u1 = *(const float2*)(base + (size_t)(k + 1) * D + 2 * lane);
            sx += w0 * u0.x; sy += w0 * u0.y;
            tx_ += w1 * u1.x; ty_ += w1 * u1.y;
        }
        {
            float w = sc[62];
            float2 u = *(const float2*)(base + (size_t)62 * D + 2 * lane);
            sx += w * u.x; sy += w * u.y;
        }
        s_sm[warp][2 * lane]     = sx + tx_;
        s_sm[warp][2 * lane + 1] = sy + ty_;
    }
    __syncwarp();

    float r = 0.f;
    #pragma unroll
    for (int rep = 0; rep < 2; rep++) {
        int o = lane + 32 * rep;
        if (o < D) {
            float a = gbs[o];
            #pragma unroll 10
            for (int d = 0; d < D; d++)
                a += s_sm[warp][d] * Wgs[o * 51 + d];
            float f = (a > 0.f) ? a : expm1f(a);
            r += f * Wrs[o];
        }
    }
    #pragma unroll
    for (int off = 16; off; off >>= 1)
        r += __shfl_down_sync(0xffffffffu, r, off);
    if (lane == 0) out[n] = r + br[0];
}

// ============================================================
extern "C" void kernel_launch(void* const* d_in, const int* in_sizes, int n_in,
                              void* d_out, int out_size) {
    const float* query  = (const float*)d_in[0];
    const float* entity = (const float*)d_in[1];
    const float* nbr    = (const float*)d_in[2];
    const float* scores = (const float*)d_in[3];
    const float* Wp     = (const float*)d_in[4];
    const float* bp     = (const float*)d_in[5];
    const float* Wbil   = (const float*)d_in[6];
    const float* bbil   = (const float*)d_in[7];
    const float* Wg     = (const float*)d_in[8];
    const float* gbias  = (const float*)d_in[9];
    const float* Wr     = (const float*)d_in[10];
    const float* br     = (const float*)d_in[11];
    float* out = (float*)d_out;

    int N = in_sizes[0] / D;
    if (N > NMAX) N = NMAX;

    prep_kernel<<<(D * D * BROW + 255) / 256, 256>>>(Wp, Wbil);
    ent_proj_kernel<<<(N + 63) / 64, 128>>>(entity, bp, N);
    dim3 bgrid((N + 63) / 64, ISPL);
    bilinear_kernel<<<bgrid, 128>>>(query, N);
    tail_kernel<<<(N + 7) / 8, 256>>>(nbr, scores, bbil, Wg, gbias, Wr, br, out, N);
}